// round 12
// baseline (speedup 1.0000x reference)
#include <cuda_runtime.h>
#include <cuda_fp16.h>
#include <math.h>

#define BB 4096
#define LL 32
#define HH 6
#define DDIM 300
#define HDD 50
#define NKC16 19       // k-chunks of 16 (K padded to 304)
#define HS 328         // half-stride of X/K/V rows: conflict-free frag loads
#define MT 64          // rows per CTA = 2 batch rows
#define GT 512         // 16 warps: 2 in M x 8 in N; warp tile 32 x 40

// Fragment-packed fp16 weights (same layout as R10/R11)
#define WB16 (NKC16 * 8 * 5 * 32)
__device__ uint2 g_Wh[5][WB16];

// smem byte offsets
#define X_OFF   0           // half [64][328] : x -> Q -> ctx -> ctx2(fp16)
#define K_OFF   41984       // half [64][328]
#define V_OFF   83968       // half [64][328]
#define CT_OFF  41984       // float [64][300] ctx2 fp32 (overlays K/V after attention)
#define SP_OFF  125952      // float [8][64]
#define SA_OFF  128000      // float [64]
#define SAL_OFF 128256      // float [64]
#define SMEM_BYTES 128512

__device__ __forceinline__ float tanh_fast(float x) {
    float y;
    asm("tanh.approx.f32 %0, %1;" : "=f"(y) : "f"(x));
    return y;
}

__device__ __forceinline__ void mma16(float c[4], const unsigned a[4],
                                      unsigned b0, unsigned b1) {
    asm volatile(
        "mma.sync.aligned.m16n8k16.row.col.f32.f16.f16.f32 "
        "{%0,%1,%2,%3},{%4,%5,%6,%7},{%8,%9},{%0,%1,%2,%3};"
        : "+f"(c[0]), "+f"(c[1]), "+f"(c[2]), "+f"(c[3])
        : "r"(a[0]), "r"(a[1]), "r"(a[2]), "r"(a[3]), "r"(b0), "r"(b1));
}

__device__ __forceinline__ void ldsm4(unsigned a[4], const __half* p) {
    unsigned addr = (unsigned)__cvta_generic_to_shared(p);
    asm volatile("ldmatrix.sync.aligned.m8n8.x4.shared.b16 {%0,%1,%2,%3}, [%4];"
                 : "=r"(a[0]), "=r"(a[1]), "=r"(a[2]), "=r"(a[3]) : "r"(addr));
}

__global__ void prep_kernel(const float* __restrict__ Wq, const float* __restrict__ Wk,
                            const float* __restrict__ Wv, const float* __restrict__ Wo,
                            const float* __restrict__ Va) {
    const float* src;
    int m = blockIdx.y;
    switch (m) {
        case 0: src = Wq; break;
        case 1: src = Wk; break;
        case 2: src = Wv; break;
        case 3: src = Wo; break;
        default: src = Va; break;
    }
    uint2* dst = g_Wh[m];
    for (int idx = blockIdx.x * blockDim.x + threadIdx.x; idx < WB16;
         idx += gridDim.x * blockDim.x) {
        int lane = idx & 31;
        int t1   = idx >> 5;
        int nc   = t1 % 5;
        int t2   = t1 / 5;
        int wn   = t2 & 7;
        int kc   = t2 >> 3;
        int gid = lane >> 2, tig = lane & 3;
        int n = wn * 40 + nc * 8 + gid;
        int k = kc * 16 + 2 * tig;
        float w0 = 0.f, w1 = 0.f, w2 = 0.f, w3 = 0.f;
        if (n < DDIM) {
            if (k < DDIM)     w0 = src[n * DDIM + k];
            if (k + 1 < DDIM) w1 = src[n * DDIM + k + 1];
            if (k + 8 < DDIM) w2 = src[n * DDIM + k + 8];
            if (k + 9 < DDIM) w3 = src[n * DDIM + k + 9];
        }
        uint2 f;
        f.x = (unsigned)__half_as_ushort(__float2half_rn(w0)) |
              ((unsigned)__half_as_ushort(__float2half_rn(w1)) << 16);
        f.y = (unsigned)__half_as_ushort(__float2half_rn(w2)) |
              ((unsigned)__half_as_ushort(__float2half_rn(w3)) << 16);
        dst[idx] = f;
    }
}

// one k-chunk: consume b[], then refill b[] with kc+2
__device__ __forceinline__ void gstep(const __half* __restrict__ pa0,
                                      const __half* __restrict__ pa1,
                                      const uint2* __restrict__ wb0,
                                      int kc, uint2 b[5], float c[2][5][4]) {
    uint2 nb[5];
    const bool ld = (kc + 2 < NKC16);
    const uint2* w2 = wb0 + (size_t)(kc + 2) * (8 * 5 * 32);
    #pragma unroll
    for (int nc = 0; nc < 5; ++nc)
        nb[nc] = ld ? w2[nc * 32] : make_uint2(0u, 0u);

    unsigned a[2][4];
    ldsm4(a[0], pa0 + kc * 16);
    ldsm4(a[1], pa1 + kc * 16);
    #pragma unroll
    for (int nc = 0; nc < 5; ++nc)
        #pragma unroll
        for (int mf = 0; mf < 2; ++mf)
            mma16(c[mf][nc], a[mf], b[nc].x, b[nc].y);
    #pragma unroll
    for (int nc = 0; nc < 5; ++nc) b[nc] = nb[nc];
}

// GEMM mainloop: warp tile 32x40, A via ldmatrix.x4, B depth-2 register ring
__device__ __forceinline__ void gemm_main(const __half* __restrict__ pa0,
                                          const __half* __restrict__ pa1,
                                          const uint2* __restrict__ wb0,
                                          float c[2][5][4]) {
    #pragma unroll
    for (int mf = 0; mf < 2; ++mf)
        #pragma unroll
        for (int nc = 0; nc < 5; ++nc)
            #pragma unroll
            for (int i = 0; i < 4; ++i) c[mf][nc][i] = 0.f;

    uint2 b0[5], b1[5];
    #pragma unroll
    for (int nc = 0; nc < 5; ++nc) {
        b0[nc] = wb0[nc * 32];
        b1[nc] = wb0[(size_t)(8 * 5 * 32) + nc * 32];
    }

    #pragma unroll 1
    for (int kb = 0; kb < 9; ++kb) {          // kc 0..17
        int kc = kb * 2;
        gstep(pa0, pa1, wb0, kc + 0, b0, c);
        gstep(pa0, pa1, wb0, kc + 1, b1, c);
    }
    gstep(pa0, pa1, wb0, 18, b0, c);          // kc 18 (last)
}

__global__ __launch_bounds__(GT, 1)
void fused_kernel(const int* __restrict__ title,
                  const float* __restrict__ emb,
                  const float* __restrict__ pos,
                  const float* __restrict__ bq,
                  const float* __restrict__ bk,
                  const float* __restrict__ bv,
                  const float* __restrict__ bo,
                  const float* __restrict__ ba,
                  const float* __restrict__ qw,
                  float* __restrict__ out) {
    extern __shared__ char smraw[];
    __half* Xsh = (__half*)(smraw + X_OFF);
    __half* SKh = (__half*)(smraw + K_OFF);
    __half* SVh = (__half*)(smraw + V_OFF);
    float*  CT  = (float*)(smraw + CT_OFF);     // stride 300
    float*  SP  = (float*)(smraw + SP_OFF);
    float*  SA  = (float*)(smraw + SA_OFF);
    float*  SAL = (float*)(smraw + SAL_OFF);
    __shared__ int toks[MT];

    const int tid = threadIdx.x;
    const int lane = tid & 31, wid = tid >> 5;
    const int gid = lane >> 2, tig = lane & 3;
    const int wm = wid >> 3, wn = wid & 7;     // 2 x 8 warp grid
    const int r0 = blockIdx.x * MT;

    const int lrow = (lane & 15);
    const int lcol = (lane >> 4) << 3;

    if (tid < MT) toks[tid] = title[r0 + tid];
    __syncthreads();

    // ---- gather x = fp16(emb[tok] + pos); cols 300..327 zero ----
    for (int idx = tid; idx < MT * 82; idx += GT) {
        int r = idx / 82, j = idx - r * 82;
        uint2 o = make_uint2(0u, 0u);
        if (j < 75) {
            float4 e = *(const float4*)&emb[(size_t)toks[r] * DDIM + 4 * j];
            float4 p = *(const float4*)&pos[(r & (LL - 1)) * DDIM + 4 * j];
            __half2 h0 = __floats2half2_rn(e.x + p.x, e.y + p.y);
            __half2 h1 = __floats2half2_rn(e.z + p.z, e.w + p.w);
            o.x = *(unsigned*)&h0;
            o.y = *(unsigned*)&h1;
        }
        *(uint2*)&Xsh[r * HS + 4 * j] = o;
    }
    __syncthreads();

    float c[2][5][4];
    const __half* paX0 = Xsh + (wm * 32 + lrow) * HS + lcol;
    const __half* paX1 = Xsh + (wm * 32 + 16 + lrow) * HS + lcol;

    // ---- K = x @ Wk^T + bk -> SKh ----
    gemm_main(paX0, paX1, g_Wh[1] + (size_t)wn * 5 * 32 + lane, c);
    #pragma unroll
    for (int mf = 0; mf < 2; ++mf)
        #pragma unroll
        for (int nc = 0; nc < 5; ++nc) {
            int n = wn * 40 + nc * 8 + 2 * tig;
            if (n < DDIM) {
                float b0 = bk[n], b1 = bk[n + 1];
                #pragma unroll
                for (int h = 0; h < 2; ++h) {
                    int r = wm * 32 + mf * 16 + gid + h * 8;
                    *(__half2*)&SKh[r * HS + n] =
                        __floats2half2_rn(c[mf][nc][2 * h] + b0, c[mf][nc][2 * h + 1] + b1);
                }
            }
        }

    // ---- V = x @ Wv^T + bv -> SVh ----
    gemm_main(paX0, paX1, g_Wh[2] + (size_t)wn * 5 * 32 + lane, c);
    #pragma unroll
    for (int mf = 0; mf < 2; ++mf)
        #pragma unroll
        for (int nc = 0; nc < 5; ++nc) {
            int n = wn * 40 + nc * 8 + 2 * tig;
            if (n < DDIM) {
                float b0 = bv[n], b1 = bv[n + 1];
                #pragma unroll
                for (int h = 0; h < 2; ++h) {
                    int r = wm * 32 + mf * 16 + gid + h * 8;
                    *(__half2*)&SVh[r * HS + n] =
                        __floats2half2_rn(c[mf][nc][2 * h] + b0, c[mf][nc][2 * h + 1] + b1);
                }
            }
        }

    // ---- Q = (x @ Wq^T + bq)/sqrt(HD) -> Xsh ----
    gemm_main(paX0, paX1, g_Wh[0] + (size_t)wn * 5 * 32 + lane, c);
    const float rs = rsqrtf((float)HDD);
    __syncthreads();                 // all warps done reading x
    #pragma unroll
    for (int mf = 0; mf < 2; ++mf)
        #pragma unroll
        for (int nc = 0; nc < 5; ++nc) {
            int n = wn * 40 + nc * 8 + 2 * tig;
            if (n < DDIM) {
                float b0 = bq[n], b1 = bq[n + 1];
                #pragma unroll
                for (int h = 0; h < 2; ++h) {
                    int r = wm * 32 + mf * 16 + gid + h * 8;
                    *(__half2*)&Xsh[r * HS + n] =
                        __floats2half2_rn((c[mf][nc][2 * h] + b0) * rs,
                                          (c[mf][nc][2 * h + 1] + b1) * rs);
                }
            }
        }
    __syncthreads();

    // ---- attention: 12 (brow,head) tasks over 16 warps (one round) ----
    if (wid < 2 * HH) {
        int br = wid / HH, h = wid - HH * (wid / HH);
        int off = h * HDD;
        const __half* Qb = Xsh + (br * LL) * HS;
        const __half* Kb = SKh + (br * LL) * HS;
        const __half* Vb = SVh + (br * LL) * HS;
        const int i = lane;
        float s[LL];
        #pragma unroll
        for (int j = 0; j < LL; ++j) s[j] = 0.f;
        for (int hd2 = 0; hd2 < HDD / 2; ++hd2) {
            float2 q2 = __half22float2(*(const __half2*)&Qb[i * HS + off + 2 * hd2]);
            #pragma unroll
            for (int j = 0; j < LL; ++j) {
                float2 k2 = __half22float2(*(const __half2*)&Kb[j * HS + off + 2 * hd2]);
                s[j] = fmaf(q2.x, k2.x, fmaf(q2.y, k2.y, s[j]));
            }
        }
        float m = -1e30f;
        #pragma unroll
        for (int j = 0; j < LL; ++j) m = fmaxf(m, s[j]);
        float sum = 0.f;
        #pragma unroll
        for (int j = 0; j < LL; ++j) { s[j] = __expf(s[j] - m); sum += s[j]; }
        float inv = 1.f / sum;
        #pragma unroll
        for (int j = 0; j < LL; ++j) s[j] *= inv;
        for (int hd2 = 0; hd2 < HDD / 2; ++hd2) {
            float cx = 0.f, cy = 0.f;
            #pragma unroll
            for (int j = 0; j < LL; ++j) {
                float2 v2 = __half22float2(*(const __half2*)&Vb[j * HS + off + 2 * hd2]);
                cx = fmaf(s[j], v2.x, cx);
                cy = fmaf(s[j], v2.y, cy);
            }
            *(__half2*)&Xsh[(br * LL + i) * HS + off + 2 * hd2] = __floats2half2_rn(cx, cy);
        }
    }
    __syncthreads();

    // ---- ctx2 = ctx @ Wo^T + bo : fp32 -> CT, fp16 -> Xsh ----
    gemm_main(paX0, paX1, g_Wh[3] + (size_t)wn * 5 * 32 + lane, c);
    __syncthreads();                 // all warps done reading ctx
    #pragma unroll
    for (int mf = 0; mf < 2; ++mf)
        #pragma unroll
        for (int nc = 0; nc < 5; ++nc) {
            int n = wn * 40 + nc * 8 + 2 * tig;
            if (n < DDIM) {
                float b0 = bo[n], b1 = bo[n + 1];
                #pragma unroll
                for (int h = 0; h < 2; ++h) {
                    int r = wm * 32 + mf * 16 + gid + h * 8;
                    float v0 = c[mf][nc][2 * h] + b0;
                    float v1 = c[mf][nc][2 * h + 1] + b1;
                    *(float2*)&CT[r * 300 + n] = make_float2(v0, v1);
                    *(__half2*)&Xsh[r * HS + n] = __floats2half2_rn(v0, v1);
                }
            }
        }
    __syncthreads();

    // ---- scores: a[l] = sum_n tanh(ctx2 @ Va^T + ba)[l][n] * qw[n] ----
    gemm_main(paX0, paX1, g_Wh[4] + (size_t)wn * 5 * 32 + lane, c);
    {
        float p[2][2];
        #pragma unroll
        for (int mf = 0; mf < 2; ++mf) { p[mf][0] = 0.f; p[mf][1] = 0.f; }
        #pragma unroll
        for (int mf = 0; mf < 2; ++mf)
            #pragma unroll
            for (int nc = 0; nc < 5; ++nc)
                #pragma unroll
                for (int i = 0; i < 4; ++i) {
                    int n = wn * 40 + nc * 8 + 2 * tig + (i & 1);
                    if (n < DDIM) {
                        float tv = tanh_fast(c[mf][nc][i] + ba[n]);
                        p[mf][i >> 1] = fmaf(tv, qw[n], p[mf][i >> 1]);
                    }
                }
        #pragma unroll
        for (int mf = 0; mf < 2; ++mf)
            #pragma unroll
            for (int h = 0; h < 2; ++h) {
                float v = p[mf][h];
                v += __shfl_xor_sync(0xffffffffu, v, 1);
                v += __shfl_xor_sync(0xffffffffu, v, 2);
                p[mf][h] = v;
            }
        if (tig == 0) {
            #pragma unroll
            for (int mf = 0; mf < 2; ++mf)
                #pragma unroll
                for (int h = 0; h < 2; ++h) {
                    int r = wm * 32 + mf * 16 + gid + h * 8;
                    SP[wn * MT + r] = p[mf][h];
                }
        }
    }
    __syncthreads();
    if (tid < MT) {
        float s = 0.f;
        #pragma unroll
        for (int w = 0; w < 8; ++w) s += SP[w * MT + tid];
        SA[tid] = s;
    }
    __syncthreads();

    if (wid < 2) {      // one warp per batch row
        float v = SA[wid * LL + lane];
        float m = v;
        #pragma unroll
        for (int o = 16; o; o >>= 1) m = fmaxf(m, __shfl_xor_sync(0xffffffffu, m, o));
        float e = __expf(v - m);
        float sum = e;
        #pragma unroll
        for (int o = 16; o; o >>= 1) sum += __shfl_xor_sync(0xffffffffu, sum, o);
        SAL[wid * LL + lane] = e / sum;
    }
    __syncthreads();

    for (int idx = tid; idx < 2 * DDIM; idx += GT) {
        int bb = idx / DDIM, d = idx - bb * DDIM;
        float o = 0.f;
        #pragma unroll
        for (int l = 0; l < LL; ++l)
            o = fmaf(SAL[bb * LL + l], CT[(bb * LL + l) * 300 + d], o);
        out[(size_t)(blockIdx.x * 2 + bb) * DDIM + d] = o;
    }
}

extern "C" void kernel_launch(void* const* d_in, const int* in_sizes, int n_in,
                              void* d_out, int out_size) {
    const int*   title = (const int*)  d_in[0];
    const float* emb   = (const float*)d_in[1];
    const float* pos   = (const float*)d_in[2];
    const float* Wq    = (const float*)d_in[3];
    const float* bq    = (const float*)d_in[4];
    const float* Wk    = (const float*)d_in[5];
    const float* bk    = (const float*)d_in[6];
    const float* Wv    = (const float*)d_in[7];
    const float* bv    = (const float*)d_in[8];
    const float* Wo    = (const float*)d_in[9];
    const float* bo    = (const float*)d_in[10];
    const float* Va    = (const float*)d_in[11];
    const float* ba    = (const float*)d_in[12];
    const float* qw    = (const float*)d_in[13];
    float* out = (float*)d_out;

    cudaFuncSetAttribute(fused_kernel,
                         cudaFuncAttributeMaxDynamicSharedMemorySize, SMEM_BYTES);

    dim3 pgrid(48, 5);
    prep_kernel<<<pgrid, 256>>>(Wq, Wk, Wv, Wo, Va);

    fused_kernel<<<BB * LL / MT, GT, SMEM_BYTES>>>(title, emb, pos,
                                                   bq, bk, bv, bo, ba, qw, out);
}

// round 15
// speedup vs baseline: 1.4663x; 1.4663x over previous
#include <cuda_runtime.h>
#include <cuda_fp16.h>
#include <math.h>

#define BB 4096
#define LL 32
#define HH 6
#define DDIM 300
#define HDD 50
#define NKC16 19       // k-chunks of 16 (K padded to 304)
#define HS 328         // half-stride of flat X rows: conflict-free frag loads
#define PS 392         // half-stride of head-padded Q/K/V rows (6*64 + 8 pad)
#define MT 64          // rows per CTA = 2 batch rows
#define GT 512         // 16 warps: 2 in M x 8 in N; warp tile 32 x 40

// Fragment-packed fp16 weights (same layout as R10/R11)
#define WB16 (NKC16 * 8 * 5 * 32)
__device__ uint2 g_Wh[5][WB16];

// smem byte offsets
#define X_OFF   0           // half [64][328] : x -> ctx -> ctx2(fp16)
#define QP_OFF  41984       // half [64][392] head-padded Q
#define KP_OFF  92160       // half [64][392] head-padded K
#define VP_OFF  142336      // half [64][392] head-padded V
#define CT_OFF  92160       // float [64][300] ctx2 fp32 (overlays K/V after attention)
#define SP_OFF  192512      // float [8][64]
#define SA_OFF  194560      // float [64]
#define SAL_OFF 194816      // float [64]
#define SMEM_BYTES 195072

__device__ __forceinline__ float tanh_fast(float x) {
    float y;
    asm("tanh.approx.f32 %0, %1;" : "=f"(y) : "f"(x));
    return y;
}

__device__ __forceinline__ void mma16(float c[4], const unsigned a[4],
                                      unsigned b0, unsigned b1) {
    asm volatile(
        "mma.sync.aligned.m16n8k16.row.col.f32.f16.f16.f32 "
        "{%0,%1,%2,%3},{%4,%5,%6,%7},{%8,%9},{%0,%1,%2,%3};"
        : "+f"(c[0]), "+f"(c[1]), "+f"(c[2]), "+f"(c[3])
        : "r"(a[0]), "r"(a[1]), "r"(a[2]), "r"(a[3]), "r"(b0), "r"(b1));
}

__device__ __forceinline__ void ldsm4(unsigned a[4], const __half* p) {
    unsigned addr = (unsigned)__cvta_generic_to_shared(p);
    asm volatile("ldmatrix.sync.aligned.m8n8.x4.shared.b16 {%0,%1,%2,%3}, [%4];"
                 : "=r"(a[0]), "=r"(a[1]), "=r"(a[2]), "=r"(a[3]) : "r"(addr));
}

__device__ __forceinline__ void ldsm2(unsigned b[2], const __half* p) {
    unsigned addr = (unsigned)__cvta_generic_to_shared(p);
    asm volatile("ldmatrix.sync.aligned.m8n8.x2.shared.b16 {%0,%1}, [%2];"
                 : "=r"(b[0]), "=r"(b[1]) : "r"(addr));
}

__device__ __forceinline__ void ldsm2t(unsigned b[2], const __half* p) {
    unsigned addr = (unsigned)__cvta_generic_to_shared(p);
    asm volatile("ldmatrix.sync.aligned.m8n8.x2.trans.shared.b16 {%0,%1}, [%2];"
                 : "=r"(b[0]), "=r"(b[1]) : "r"(addr));
}

__device__ __forceinline__ unsigned packh2(float lo, float hi) {
    __half2 h = __floats2half2_rn(lo, hi);
    return *(unsigned*)&h;
}

__global__ void prep_kernel(const float* __restrict__ Wq, const float* __restrict__ Wk,
                            const float* __restrict__ Wv, const float* __restrict__ Wo,
                            const float* __restrict__ Va) {
    const float* src;
    int m = blockIdx.y;
    switch (m) {
        case 0: src = Wq; break;
        case 1: src = Wk; break;
        case 2: src = Wv; break;
        case 3: src = Wo; break;
        default: src = Va; break;
    }
    uint2* dst = g_Wh[m];
    for (int idx = blockIdx.x * blockDim.x + threadIdx.x; idx < WB16;
         idx += gridDim.x * blockDim.x) {
        int lane = idx & 31;
        int t1   = idx >> 5;
        int nc   = t1 % 5;
        int t2   = t1 / 5;
        int wn   = t2 & 7;
        int kc   = t2 >> 3;
        int gid = lane >> 2, tig = lane & 3;
        int n = wn * 40 + nc * 8 + gid;
        int k = kc * 16 + 2 * tig;
        float w0 = 0.f, w1 = 0.f, w2 = 0.f, w3 = 0.f;
        if (n < DDIM) {
            if (k < DDIM)     w0 = src[n * DDIM + k];
            if (k + 1 < DDIM) w1 = src[n * DDIM + k + 1];
            if (k + 8 < DDIM) w2 = src[n * DDIM + k + 8];
            if (k + 9 < DDIM) w3 = src[n * DDIM + k + 9];
        }
        uint2 f;
        f.x = (unsigned)__half_as_ushort(__float2half_rn(w0)) |
              ((unsigned)__half_as_ushort(__float2half_rn(w1)) << 16);
        f.y = (unsigned)__half_as_ushort(__float2half_rn(w2)) |
              ((unsigned)__half_as_ushort(__float2half_rn(w3)) << 16);
        dst[idx] = f;
    }
}

// GEMM mainloop (R11 depth-1): warp tile 32x40, A via ldmatrix.x4
__device__ __forceinline__ void gemm_main(const __half* __restrict__ pa0,
                                          const __half* __restrict__ pa1,
                                          const uint2* __restrict__ wb0,
                                          float c[2][5][4]) {
    #pragma unroll
    for (int mf = 0; mf < 2; ++mf)
        #pragma unroll
        for (int nc = 0; nc < 5; ++nc)
            #pragma unroll
            for (int i = 0; i < 4; ++i) c[mf][nc][i] = 0.f;

    uint2 bcur[5];
    #pragma unroll
    for (int nc = 0; nc < 5; ++nc) bcur[nc] = wb0[nc * 32];

    #pragma unroll 2
    for (int kc = 0; kc < NKC16; ++kc) {
        uint2 bnxt[5];
        if (kc + 1 < NKC16) {
            const uint2* w2 = wb0 + (size_t)(kc + 1) * (8 * 5 * 32);
            #pragma unroll
            for (int nc = 0; nc < 5; ++nc) bnxt[nc] = w2[nc * 32];
        }
        unsigned a[2][4];
        ldsm4(a[0], pa0 + kc * 16);
        ldsm4(a[1], pa1 + kc * 16);
        #pragma unroll
        for (int nc = 0; nc < 5; ++nc)
            #pragma unroll
            for (int mf = 0; mf < 2; ++mf)
                mma16(c[mf][nc], a[mf], bcur[nc].x, bcur[nc].y);
        #pragma unroll
        for (int nc = 0; nc < 5; ++nc) bcur[nc] = bnxt[nc];
    }
}

__global__ __launch_bounds__(GT, 1)
void fused_kernel(const int* __restrict__ title,
                  const float* __restrict__ emb,
                  const float* __restrict__ pos,
                  const float* __restrict__ bq,
                  const float* __restrict__ bk,
                  const float* __restrict__ bv,
                  const float* __restrict__ bo,
                  const float* __restrict__ ba,
                  const float* __restrict__ qw,
                  float* __restrict__ out) {
    extern __shared__ char smraw[];
    __half* Xsh = (__half*)(smraw + X_OFF);
    __half* QP  = (__half*)(smraw + QP_OFF);
    __half* KP  = (__half*)(smraw + KP_OFF);
    __half* VP  = (__half*)(smraw + VP_OFF);
    float*  CT  = (float*)(smraw + CT_OFF);     // stride 300
    float*  SP  = (float*)(smraw + SP_OFF);
    float*  SA  = (float*)(smraw + SA_OFF);
    float*  SAL = (float*)(smraw + SAL_OFF);
    __shared__ int toks[MT];

    const int tid = threadIdx.x;
    const int lane = tid & 31, wid = tid >> 5;
    const int gid = lane >> 2, tig = lane & 3;
    const int wm = wid >> 3, wn = wid & 7;     // 2 x 8 warp grid
    const int r0 = blockIdx.x * MT;

    const int lrow = (lane & 15);
    const int lcol = (lane >> 4) << 3;

    if (tid < MT) toks[tid] = title[r0 + tid];
    __syncthreads();

    // ---- zero head-padded Q/K/V regions (pads must be 0 for mma) ----
    {
        uint4* z = (uint4*)(smraw + QP_OFF);
        const int nz = (VP_OFF + MT * PS * 2 - QP_OFF) / 16;   // 9408
        for (int i = tid; i < nz; i += GT) z[i] = make_uint4(0u, 0u, 0u, 0u);
    }

    // ---- gather x = fp16(emb[tok] + pos); cols 300..327 zero ----
    for (int idx = tid; idx < MT * 82; idx += GT) {
        int r = idx / 82, j = idx - r * 82;
        uint2 o = make_uint2(0u, 0u);
        if (j < 75) {
            float4 e = *(const float4*)&emb[(size_t)toks[r] * DDIM + 4 * j];
            float4 p = *(const float4*)&pos[(r & (LL - 1)) * DDIM + 4 * j];
            __half2 h0 = __floats2half2_rn(e.x + p.x, e.y + p.y);
            __half2 h1 = __floats2half2_rn(e.z + p.z, e.w + p.w);
            o.x = *(unsigned*)&h0;
            o.y = *(unsigned*)&h1;
        }
        *(uint2*)&Xsh[r * HS + 4 * j] = o;
    }
    __syncthreads();

    float c[2][5][4];
    const __half* paX0 = Xsh + (wm * 32 + lrow) * HS + lcol;
    const __half* paX1 = Xsh + (wm * 32 + 16 + lrow) * HS + lcol;

    // ---- K = x @ Wk^T + bk -> KP (head-padded) ----
    gemm_main(paX0, paX1, g_Wh[1] + (size_t)wn * 5 * 32 + lane, c);
    #pragma unroll
    for (int mf = 0; mf < 2; ++mf)
        #pragma unroll
        for (int nc = 0; nc < 5; ++nc) {
            int n = wn * 40 + nc * 8 + 2 * tig;
            if (n < DDIM) {
                int hh = n / 50, hd = n - 50 * hh;
                int col = hh * 64 + hd;
                float b0 = bk[n], b1 = bk[n + 1];
                #pragma unroll
                for (int h = 0; h < 2; ++h) {
                    int r = wm * 32 + mf * 16 + gid + h * 8;
                    *(__half2*)&KP[r * PS + col] =
                        __floats2half2_rn(c[mf][nc][2 * h] + b0, c[mf][nc][2 * h + 1] + b1);
                }
            }
        }

    // ---- V = x @ Wv^T + bv -> VP ----
    gemm_main(paX0, paX1, g_Wh[2] + (size_t)wn * 5 * 32 + lane, c);
    #pragma unroll
    for (int mf = 0; mf < 2; ++mf)
        #pragma unroll
        for (int nc = 0; nc < 5; ++nc) {
            int n = wn * 40 + nc * 8 + 2 * tig;
            if (n < DDIM) {
                int hh = n / 50, hd = n - 50 * hh;
                int col = hh * 64 + hd;
                float b0 = bv[n], b1 = bv[n + 1];
                #pragma unroll
                for (int h = 0; h < 2; ++h) {
                    int r = wm * 32 + mf * 16 + gid + h * 8;
                    *(__half2*)&VP[r * PS + col] =
                        __floats2half2_rn(c[mf][nc][2 * h] + b0, c[mf][nc][2 * h + 1] + b1);
                }
            }
        }

    // ---- Q = (x @ Wq^T + bq)/sqrt(HD) -> QP ----
    gemm_main(paX0, paX1, g_Wh[0] + (size_t)wn * 5 * 32 + lane, c);
    const float rs = rsqrtf((float)HDD);
    #pragma unroll
    for (int mf = 0; mf < 2; ++mf)
        #pragma unroll
        for (int nc = 0; nc < 5; ++nc) {
            int n = wn * 40 + nc * 8 + 2 * tig;
            if (n < DDIM) {
                int hh = n / 50, hd = n - 50 * hh;
                int col = hh * 64 + hd;
                float b0 = bq[n], b1 = bq[n + 1];
                #pragma unroll
                for (int h = 0; h < 2; ++h) {
                    int r = wm * 32 + mf * 16 + gid + h * 8;
                    *(__half2*)&QP[r * PS + col] =
                        __floats2half2_rn((c[mf][nc][2 * h] + b0) * rs,
                                          (c[mf][nc][2 * h + 1] + b1) * rs);
                }
            }
        }
    __syncthreads();

    // ---- tensor-core attention: 12 (brow,head) tasks; ctx -> Xsh (flat fp16) ----
    if (wid < 2 * HH) {
        int br = wid / HH, h = wid - HH * (wid / HH);
        const __half* Qb = QP + (br * LL) * PS + h * 64;
        const __half* Kb = KP + (br * LL) * PS + h * 64;
        const __half* Vb = VP + (br * LL) * PS + h * 64;
        const int l15 = lane & 15;

        // S = Q K^T  (M=32, N=32, K=64 padded)
        float cS[2][4][4];
        #pragma unroll
        for (int mf = 0; mf < 2; ++mf)
            #pragma unroll
            for (int nb = 0; nb < 4; ++nb)
                #pragma unroll
                for (int i = 0; i < 4; ++i) cS[mf][nb][i] = 0.f;
        #pragma unroll
        for (int kk = 0; kk < 4; ++kk) {
            unsigned aq[2][4];
            ldsm4(aq[0], Qb + lrow * PS + lcol + kk * 16);
            ldsm4(aq[1], Qb + (16 + lrow) * PS + lcol + kk * 16);
            #pragma unroll
            for (int nb = 0; nb < 4; ++nb) {
                unsigned bk2[2];
                ldsm2(bk2, Kb + (nb * 8 + (lane & 7)) * PS + kk * 16 + ((l15 >> 3) << 3));
                #pragma unroll
                for (int mf = 0; mf < 2; ++mf)
                    mma16(cS[mf][nb], aq[mf], bk2[0], bk2[1]);
            }
        }

        // register softmax over rows (row owned by 4 lanes: tig 0..3)
        #pragma unroll
        for (int mf = 0; mf < 2; ++mf)
            #pragma unroll
            for (int rsel = 0; rsel < 2; ++rsel) {
                float m = -1e30f;
                #pragma unroll
                for (int nb = 0; nb < 4; ++nb)
                    #pragma unroll
                    for (int p = 0; p < 2; ++p)
                        m = fmaxf(m, cS[mf][nb][2 * rsel + p]);
                m = fmaxf(m, __shfl_xor_sync(0xffffffffu, m, 1));
                m = fmaxf(m, __shfl_xor_sync(0xffffffffu, m, 2));
                float sum = 0.f;
                #pragma unroll
                for (int nb = 0; nb < 4; ++nb)
                    #pragma unroll
                    for (int p = 0; p < 2; ++p) {
                        float e = __expf(cS[mf][nb][2 * rsel + p] - m);
                        cS[mf][nb][2 * rsel + p] = e;
                        sum += e;
                    }
                sum += __shfl_xor_sync(0xffffffffu, sum, 1);
                sum += __shfl_xor_sync(0xffffffffu, sum, 2);
                float inv = 1.f / sum;
                #pragma unroll
                for (int nb = 0; nb < 4; ++nb)
                    #pragma unroll
                    for (int p = 0; p < 2; ++p)
                        cS[mf][nb][2 * rsel + p] *= inv;
            }

        // repack P (C layout -> A fragments), fp16
        unsigned aP[2][2][4];
        #pragma unroll
        for (int mf = 0; mf < 2; ++mf)
            #pragma unroll
            for (int kk2 = 0; kk2 < 2; ++kk2) {
                aP[mf][kk2][0] = packh2(cS[mf][2 * kk2][0],     cS[mf][2 * kk2][1]);
                aP[mf][kk2][1] = packh2(cS[mf][2 * kk2][2],     cS[mf][2 * kk2][3]);
                aP[mf][kk2][2] = packh2(cS[mf][2 * kk2 + 1][0], cS[mf][2 * kk2 + 1][1]);
                aP[mf][kk2][3] = packh2(cS[mf][2 * kk2 + 1][2], cS[mf][2 * kk2 + 1][3]);
            }

        // ctx = P V  (N=64 in two groups of 32), store flat cols h*50+hd
        #pragma unroll
        for (int g = 0; g < 2; ++g) {
            float cO[2][4][4];
            #pragma unroll
            for (int mf = 0; mf < 2; ++mf)
                #pragma unroll
                for (int nb = 0; nb < 4; ++nb)
                    #pragma unroll
                    for (int i = 0; i < 4; ++i) cO[mf][nb][i] = 0.f;
            #pragma unroll
            for (int kk2 = 0; kk2 < 2; ++kk2)
                #pragma unroll
                for (int nbl = 0; nbl < 4; ++nbl) {
                    unsigned bv2[2];
                    ldsm2t(bv2, Vb + (kk2 * 16 + l15) * PS + (g * 4 + nbl) * 8);
                    #pragma unroll
                    for (int mf = 0; mf < 2; ++mf)
                        mma16(cO[mf][nbl], aP[mf][kk2], bv2[0], bv2[1]);
                }
            #pragma unroll
            for (int mf = 0; mf < 2; ++mf)
                #pragma unroll
                for (int nbl = 0; nbl < 4; ++nbl) {
                    int hdc = (g * 4 + nbl) * 8 + 2 * tig;
                    if (hdc < HDD) {
                        int n = h * HDD + hdc;
                        #pragma unroll
                        for (int hs2 = 0; hs2 < 2; ++hs2) {
                            int r = br * LL + mf * 16 + gid + hs2 * 8;
                            *(__half2*)&Xsh[r * HS + n] =
                                __floats2half2_rn(cO[mf][nbl][2 * hs2],
                                                  cO[mf][nbl][2 * hs2 + 1]);
                        }
                    }
                }
        }
    }
    __syncthreads();

    // ---- ctx2 = ctx @ Wo^T + bo : fp32 -> CT, fp16 -> Xsh ----
    gemm_main(paX0, paX1, g_Wh[3] + (size_t)wn * 5 * 32 + lane, c);
    __syncthreads();                 // all warps done reading ctx
    #pragma unroll
    for (int mf = 0; mf < 2; ++mf)
        #pragma unroll
        for (int nc = 0; nc < 5; ++nc) {
            int n = wn * 40 + nc * 8 + 2 * tig;
            if (n < DDIM) {
                float b0 = bo[n], b1 = bo[n + 1];
                #pragma unroll
                for (int h = 0; h < 2; ++h) {
                    int r = wm * 32 + mf * 16 + gid + h * 8;
                    float v0 = c[mf][nc][2 * h] + b0;
                    float v1 = c[mf][nc][2 * h + 1] + b1;
                    *(float2*)&CT[r * 300 + n] = make_float2(v0, v1);
                    *(__half2*)&Xsh[r * HS + n] = __floats2half2_rn(v0, v1);
                }
            }
        }
    __syncthreads();

    // ---- scores: a[l] = sum_n tanh(ctx2 @ Va^T + ba)[l][n] * qw[n] ----
    gemm_main(paX0, paX1, g_Wh[4] + (size_t)wn * 5 * 32 + lane, c);
    {
        float p[2][2];
        #pragma unroll
        for (int mf = 0; mf < 2; ++mf) { p[mf][0] = 0.f; p[mf][1] = 0.f; }
        #pragma unroll
        for (int mf = 0; mf < 2; ++mf)
            #pragma unroll
            for (int nc = 0; nc < 5; ++nc)
                #pragma unroll
                for (int i = 0; i < 4; ++i) {
                    int n = wn * 40 + nc * 8 + 2 * tig + (i & 1);
                    if (n < DDIM) {
                        float tv = tanh_fast(c[mf][nc][i] + ba[n]);
                        p[mf][i >> 1] = fmaf(tv, qw[n], p[mf][i >> 1]);
                    }
                }
        #pragma unroll
        for (int mf = 0; mf < 2; ++mf)
            #pragma unroll
            for (int h = 0; h < 2; ++h) {
                float v = p[mf][h];
                v += __shfl_xor_sync(0xffffffffu, v, 1);
                v += __shfl_xor_sync(0xffffffffu, v, 2);
                p[mf][h] = v;
            }
        if (tig == 0) {
            #pragma unroll
            for (int mf = 0; mf < 2; ++mf)
                #pragma unroll
                for (int h = 0; h < 2; ++h) {
                    int r = wm * 32 + mf * 16 + gid + h * 8;
                    SP[wn * MT + r] = p[mf][h];
                }
        }
    }
    __syncthreads();
    if (tid < MT) {
        float s = 0.f;
        #pragma unroll
        for (int w = 0; w < 8; ++w) s += SP[w * MT + tid];
        SA[tid] = s;
    }
    __syncthreads();

    if (wid < 2) {      // one warp per batch row
        float v = SA[wid * LL + lane];
        float m = v;
        #pragma unroll
        for (int o = 16; o; o >>= 1) m = fmaxf(m, __shfl_xor_sync(0xffffffffu, m, o));
        float e = __expf(v - m);
        float sum = e;
        #pragma unroll
        for (int o = 16; o; o >>= 1) sum += __shfl_xor_sync(0xffffffffu, sum, o);
        SAL[wid * LL + lane] = e / sum;
    }
    __syncthreads();

    for (int idx = tid; idx < 2 * DDIM; idx += GT) {
        int bb = idx / DDIM, d = idx - bb * DDIM;
        float o = 0.f;
        #pragma unroll
        for (int l = 0; l < LL; ++l)
            o = fmaf(SAL[bb * LL + l], CT[(bb * LL + l) * 300 + d], o);
        out[(size_t)(blockIdx.x * 2 + bb) * DDIM + d] = o;
    }
}

extern "C" void kernel_launch(void* const* d_in, const int* in_sizes, int n_in,
                              void* d_out, int out_size) {
    const int*   title = (const int*)  d_in[0];
    const float* emb   = (const float*)d_in[1];
    const float* pos   = (const float*)d_in[2];
    const float* Wq    = (const float*)d_in[3];
    const float* bq    = (const float*)d_in[4];
    const float* Wk    = (const float*)d_in[5];
    const float* bk    = (const float*)d_in[6];
    const float* Wv    = (const float*)d_in[7];
    const float* bv    = (const float*)d_in[8];
    const float* Wo    = (const float*)d_in[9];
    const float* bo    = (const float*)d_in[10];
    const float* Va    = (const float*)d_in[11];
    const float* ba    = (const float*)d_in[12];
    const float* qw    = (const float*)d_in[13];
    float* out = (float*)d_out;

    cudaFuncSetAttribute(fused_kernel,
                         cudaFuncAttributeMaxDynamicSharedMemorySize, SMEM_BYTES);

    dim3 pgrid(48, 5);
    prep_kernel<<<pgrid, 256>>>(Wq, Wk, Wv, Wo, Va);

    fused_kernel<<<BB * LL / MT, GT, SMEM_BYTES>>>(title, emb, pos,
                                                   bq, bk, bv, bo, ba, qw, out);
}

// round 16
// speedup vs baseline: 1.4732x; 1.0047x over previous
#include <cuda_runtime.h>
#include <cuda_fp16.h>
#include <math.h>

#define BB 4096
#define LL 32
#define HH 6
#define DDIM 300
#define HDD 50
#define NKC16 19       // k-chunks of 16 (K padded to 304; col 300 = bias via x[...,300]=1)
#define HS 328         // half-stride of flat X rows: conflict-free frag loads
#define PS 392         // half-stride of head-padded Q/K/V rows (6*64 + 8 pad)
#define MT 64          // rows per CTA = 2 batch rows
#define GT 512         // 16 warps: 2 in M x 8 in N; warp tile 32 x 40

// Fragment-packed fp16 weights; m: Wq*rs, Wk, Wv, Wo, Wova  (bias in k=300 col)
#define WB16 (NKC16 * 8 * 5 * 32)
__device__ uint2 g_Wh[5][WB16];
__device__ float g_Wova[DDIM * DDIM];
__device__ float g_bva[DDIM];

// smem byte offsets
#define X_OFF   0           // half [64][328] : x -> ctx  (col 300 = 1.0)
#define QP_OFF  41984       // half [64][392] head-padded Q
#define KP_OFF  92160       // half [64][392] head-padded K
#define VP_OFF  142336      // half [64][392] head-padded V
#define CT_OFF  92160       // float [64][300] ctx2 fp32 (overlays K/V after attention)
#define SP_OFF  192512      // float [8][64]
#define SA_OFF  194560      // float [64]
#define SAL_OFF 194816      // float [64]
#define SMEM_BYTES 195072

__device__ __forceinline__ float tanh_fast(float x) {
    float y;
    asm("tanh.approx.f32 %0, %1;" : "=f"(y) : "f"(x));
    return y;
}

__device__ __forceinline__ void mma16(float c[4], const unsigned a[4],
                                      unsigned b0, unsigned b1) {
    asm volatile(
        "mma.sync.aligned.m16n8k16.row.col.f32.f16.f16.f32 "
        "{%0,%1,%2,%3},{%4,%5,%6,%7},{%8,%9},{%0,%1,%2,%3};"
        : "+f"(c[0]), "+f"(c[1]), "+f"(c[2]), "+f"(c[3])
        : "r"(a[0]), "r"(a[1]), "r"(a[2]), "r"(a[3]), "r"(b0), "r"(b1));
}

__device__ __forceinline__ void ldsm4(unsigned a[4], const __half* p) {
    unsigned addr = (unsigned)__cvta_generic_to_shared(p);
    asm volatile("ldmatrix.sync.aligned.m8n8.x4.shared.b16 {%0,%1,%2,%3}, [%4];"
                 : "=r"(a[0]), "=r"(a[1]), "=r"(a[2]), "=r"(a[3]) : "r"(addr));
}

__device__ __forceinline__ void ldsm2(unsigned b[2], const __half* p) {
    unsigned addr = (unsigned)__cvta_generic_to_shared(p);
    asm volatile("ldmatrix.sync.aligned.m8n8.x2.shared.b16 {%0,%1}, [%2];"
                 : "=r"(b[0]), "=r"(b[1]) : "r"(addr));
}

__device__ __forceinline__ void ldsm2t(unsigned b[2], const __half* p) {
    unsigned addr = (unsigned)__cvta_generic_to_shared(p);
    asm volatile("ldmatrix.sync.aligned.m8n8.x2.trans.shared.b16 {%0,%1}, [%2];"
                 : "=r"(b[0]), "=r"(b[1]) : "r"(addr));
}

__device__ __forceinline__ unsigned packh2(float lo, float hi) {
    __half2 h = __floats2half2_rn(lo, hi);
    return *(unsigned*)&h;
}

// ---- prep 1: Wova = Va @ Wo  (row n: Wova[n][k] = sum_m Va[n][m]*Wo[m][k]) ----
__global__ void prep_wova(const float* __restrict__ Va, const float* __restrict__ Wo,
                          const float* __restrict__ bo, const float* __restrict__ ba) {
    __shared__ float sVa[DDIM];
    __shared__ float sred[10];
    const int n = blockIdx.x;
    const int t = threadIdx.x;          // 320 threads
    for (int i = t; i < DDIM; i += 320) sVa[i] = Va[n * DDIM + i];
    __syncthreads();
    if (t < DDIM) {
        float acc = 0.f;
        #pragma unroll 4
        for (int m = 0; m < DDIM; ++m)
            acc = fmaf(sVa[m], Wo[m * DDIM + t], acc);
        g_Wova[n * DDIM + t] = acc;
    }
    float pb = (t < DDIM) ? sVa[t] * bo[t] : 0.f;
    #pragma unroll
    for (int o = 16; o; o >>= 1) pb += __shfl_xor_sync(0xffffffffu, pb, o);
    if ((t & 31) == 0) sred[t >> 5] = pb;
    __syncthreads();
    if (t == 0) {
        float s = 0.f;
        #pragma unroll
        for (int w = 0; w < 10; ++w) s += sred[w];
        g_bva[n] = s + ba[n];
    }
}

// value of augmented weight matrix m at (n,k): k<300 -> W, k==300 -> bias, else 0
__device__ __forceinline__ float wval(int m, int n, int k,
                                      const float* src, const float* bias, float scale) {
    if (n >= DDIM) return 0.f;
    if (k < DDIM)  return ((m == 4) ? g_Wova[n * DDIM + k] : src[n * DDIM + k]) * scale;
    if (k == DDIM) return ((m == 4) ? g_bva[n] : bias[n]) * scale;
    return 0.f;
}

// ---- prep 2: fragment packing (bias col + rs folding) ----
__global__ void prep_pack(const float* __restrict__ Wq, const float* __restrict__ Wk,
                          const float* __restrict__ Wv, const float* __restrict__ Wo,
                          const float* __restrict__ bq, const float* __restrict__ bk,
                          const float* __restrict__ bv, const float* __restrict__ bo) {
    const int m = blockIdx.y;
    const float* src; const float* bias;
    switch (m) {
        case 0: src = Wq; bias = bq; break;
        case 1: src = Wk; bias = bk; break;
        case 2: src = Wv; bias = bv; break;
        case 3: src = Wo; bias = bo; break;
        default: src = Wo; bias = bo; break;   // m=4 uses g_Wova/g_bva inside wval
    }
    const float scale = (m == 0) ? rsqrtf((float)HDD) : 1.f;
    uint2* dst = g_Wh[m];
    for (int idx = blockIdx.x * blockDim.x + threadIdx.x; idx < WB16;
         idx += gridDim.x * blockDim.x) {
        int lane = idx & 31;
        int t1   = idx >> 5;
        int nc   = t1 % 5;
        int t2   = t1 / 5;
        int wn   = t2 & 7;
        int kc   = t2 >> 3;
        int gid = lane >> 2, tig = lane & 3;
        int n = wn * 40 + nc * 8 + gid;
        int k = kc * 16 + 2 * tig;
        uint2 f;
        f.x = packh2(wval(m, n, k,     src, bias, scale),
                     wval(m, n, k + 1, src, bias, scale));
        f.y = packh2(wval(m, n, k + 8, src, bias, scale),
                     wval(m, n, k + 9, src, bias, scale));
        dst[idx] = f;
    }
}

// GEMM mainloop: warp tile 32x40, A via ldmatrix.x4, B depth-1 prefetch
__device__ __forceinline__ void gemm_main(const __half* __restrict__ pa0,
                                          const __half* __restrict__ pa1,
                                          const uint2* __restrict__ wb0,
                                          float c[2][5][4]) {
    #pragma unroll
    for (int mf = 0; mf < 2; ++mf)
        #pragma unroll
        for (int nc = 0; nc < 5; ++nc)
            #pragma unroll
            for (int i = 0; i < 4; ++i) c[mf][nc][i] = 0.f;

    uint2 bcur[5];
    #pragma unroll
    for (int nc = 0; nc < 5; ++nc) bcur[nc] = wb0[nc * 32];

    #pragma unroll 2
    for (int kc = 0; kc < NKC16; ++kc) {
        uint2 bnxt[5];
        if (kc + 1 < NKC16) {
            const uint2* w2 = wb0 + (size_t)(kc + 1) * (8 * 5 * 32);
            #pragma unroll
            for (int nc = 0; nc < 5; ++nc) bnxt[nc] = w2[nc * 32];
        }
        unsigned a[2][4];
        ldsm4(a[0], pa0 + kc * 16);
        ldsm4(a[1], pa1 + kc * 16);
        #pragma unroll
        for (int nc = 0; nc < 5; ++nc)
            #pragma unroll
            for (int mf = 0; mf < 2; ++mf)
                mma16(c[mf][nc], a[mf], bcur[nc].x, bcur[nc].y);
        #pragma unroll
        for (int nc = 0; nc < 5; ++nc) bcur[nc] = bnxt[nc];
    }
}

__global__ __launch_bounds__(GT, 1)
void fused_kernel(const int* __restrict__ title,
                  const float* __restrict__ emb,
                  const float* __restrict__ pos,
                  const float* __restrict__ qw,
                  float* __restrict__ out) {
    extern __shared__ char smraw[];
    __half* Xsh = (__half*)(smraw + X_OFF);
    __half* QP  = (__half*)(smraw + QP_OFF);
    __half* KP  = (__half*)(smraw + KP_OFF);
    __half* VP  = (__half*)(smraw + VP_OFF);
    float*  CT  = (float*)(smraw + CT_OFF);     // stride 300
    float*  SP  = (float*)(smraw + SP_OFF);
    float*  SA  = (float*)(smraw + SA_OFF);
    float*  SAL = (float*)(smraw + SAL_OFF);
    __shared__ int toks[MT];

    const int tid = threadIdx.x;
    const int lane = tid & 31, wid = tid >> 5;
    const int gid = lane >> 2, tig = lane & 3;
    const int wm = wid >> 3, wn = wid & 7;     // 2 x 8 warp grid
    const int r0 = blockIdx.x * MT;

    const int lrow = (lane & 15);
    const int lcol = (lane >> 4) << 3;

    if (tid < MT) toks[tid] = title[r0 + tid];
    __syncthreads();

    // ---- zero head-padded Q/K/V regions ----
    {
        uint4* z = (uint4*)(smraw + QP_OFF);
        const int nz = (VP_OFF + MT * PS * 2 - QP_OFF) / 16;
        for (int i = tid; i < nz; i += GT) z[i] = make_uint4(0u, 0u, 0u, 0u);
    }

    // ---- gather x = fp16(emb[tok] + pos); col 300 = 1.0 (bias lane), rest 0 ----
    for (int idx = tid; idx < MT * 82; idx += GT) {
        int r = idx / 82, j = idx - r * 82;
        uint2 o = make_uint2(0u, 0u);
        if (j < 75) {
            float4 e = *(const float4*)&emb[(size_t)toks[r] * DDIM + 4 * j];
            float4 p = *(const float4*)&pos[(r & (LL - 1)) * DDIM + 4 * j];
            __half2 h0 = __floats2half2_rn(e.x + p.x, e.y + p.y);
            __half2 h1 = __floats2half2_rn(e.z + p.z, e.w + p.w);
            o.x = *(unsigned*)&h0;
            o.y = *(unsigned*)&h1;
        } else if (j == 75) {
            o.x = packh2(1.f, 0.f);           // col 300 = 1.0
        }
        *(uint2*)&Xsh[r * HS + 4 * j] = o;
    }
    __syncthreads();

    float c[2][5][4];
    const __half* paX0 = Xsh + (wm * 32 + lrow) * HS + lcol;
    const __half* paX1 = Xsh + (wm * 32 + 16 + lrow) * HS + lcol;

    // ---- K = x @ [Wk|bk] -> KP (head-padded); bias via mma ----
    gemm_main(paX0, paX1, g_Wh[1] + (size_t)wn * 5 * 32 + lane, c);
    #pragma unroll
    for (int mf = 0; mf < 2; ++mf)
        #pragma unroll
        for (int nc = 0; nc < 5; ++nc) {
            int n = wn * 40 + nc * 8 + 2 * tig;
            if (n < DDIM) {
                int hh = n / 50, hd = n - 50 * hh;
                int col = hh * 64 + hd;
                #pragma unroll
                for (int h = 0; h < 2; ++h) {
                    int r = wm * 32 + mf * 16 + gid + h * 8;
                    *(__half2*)&KP[r * PS + col] =
                        __floats2half2_rn(c[mf][nc][2 * h], c[mf][nc][2 * h + 1]);
                }
            }
        }

    // ---- V = x @ [Wv|bv] -> VP ----
    gemm_main(paX0, paX1, g_Wh[2] + (size_t)wn * 5 * 32 + lane, c);
    #pragma unroll
    for (int mf = 0; mf < 2; ++mf)
        #pragma unroll
        for (int nc = 0; nc < 5; ++nc) {
            int n = wn * 40 + nc * 8 + 2 * tig;
            if (n < DDIM) {
                int hh = n / 50, hd = n - 50 * hh;
                int col = hh * 64 + hd;
                #pragma unroll
                for (int h = 0; h < 2; ++h) {
                    int r = wm * 32 + mf * 16 + gid + h * 8;
                    *(__half2*)&VP[r * PS + col] =
                        __floats2half2_rn(c[mf][nc][2 * h], c[mf][nc][2 * h + 1]);
                }
            }
        }

    // ---- Q = x @ [Wq*rs|bq*rs] -> QP ----
    gemm_main(paX0, paX1, g_Wh[0] + (size_t)wn * 5 * 32 + lane, c);
    #pragma unroll
    for (int mf = 0; mf < 2; ++mf)
        #pragma unroll
        for (int nc = 0; nc < 5; ++nc) {
            int n = wn * 40 + nc * 8 + 2 * tig;
            if (n < DDIM) {
                int hh = n / 50, hd = n - 50 * hh;
                int col = hh * 64 + hd;
                #pragma unroll
                for (int h = 0; h < 2; ++h) {
                    int r = wm * 32 + mf * 16 + gid + h * 8;
                    *(__half2*)&QP[r * PS + col] =
                        __floats2half2_rn(c[mf][nc][2 * h], c[mf][nc][2 * h + 1]);
                }
            }
        }
    __syncthreads();

    // ---- tensor-core attention: 12 (brow,head) tasks; ctx -> Xsh (cols < 300) ----
    if (wid < 2 * HH) {
        int br = wid / HH, h = wid - HH * (wid / HH);
        const __half* Qb = QP + (br * LL) * PS + h * 64;
        const __half* Kb = KP + (br * LL) * PS + h * 64;
        const __half* Vb = VP + (br * LL) * PS + h * 64;
        const int l15 = lane & 15;

        float cS[2][4][4];
        #pragma unroll
        for (int mf = 0; mf < 2; ++mf)
            #pragma unroll
            for (int nb = 0; nb < 4; ++nb)
                #pragma unroll
                for (int i = 0; i < 4; ++i) cS[mf][nb][i] = 0.f;
        #pragma unroll
        for (int kk = 0; kk < 4; ++kk) {
            unsigned aq[2][4];
            ldsm4(aq[0], Qb + lrow * PS + lcol + kk * 16);
            ldsm4(aq[1], Qb + (16 + lrow) * PS + lcol + kk * 16);
            #pragma unroll
            for (int nb = 0; nb < 4; ++nb) {
                unsigned bk2[2];
                ldsm2(bk2, Kb + (nb * 8 + (lane & 7)) * PS + kk * 16 + ((l15 >> 3) << 3));
                #pragma unroll
                for (int mf = 0; mf < 2; ++mf)
                    mma16(cS[mf][nb], aq[mf], bk2[0], bk2[1]);
            }
        }

        #pragma unroll
        for (int mf = 0; mf < 2; ++mf)
            #pragma unroll
            for (int rsel = 0; rsel < 2; ++rsel) {
                float m = -1e30f;
                #pragma unroll
                for (int nb = 0; nb < 4; ++nb)
                    #pragma unroll
                    for (int p = 0; p < 2; ++p)
                        m = fmaxf(m, cS[mf][nb][2 * rsel + p]);
                m = fmaxf(m, __shfl_xor_sync(0xffffffffu, m, 1));
                m = fmaxf(m, __shfl_xor_sync(0xffffffffu, m, 2));
                float sum = 0.f;
                #pragma unroll
                for (int nb = 0; nb < 4; ++nb)
                    #pragma unroll
                    for (int p = 0; p < 2; ++p) {
                        float e = __expf(cS[mf][nb][2 * rsel + p] - m);
                        cS[mf][nb][2 * rsel + p] = e;
                        sum += e;
                    }
                sum += __shfl_xor_sync(0xffffffffu, sum, 1);
                sum += __shfl_xor_sync(0xffffffffu, sum, 2);
                float inv = 1.f / sum;
                #pragma unroll
                for (int nb = 0; nb < 4; ++nb)
                    #pragma unroll
                    for (int p = 0; p < 2; ++p)
                        cS[mf][nb][2 * rsel + p] *= inv;
            }

        unsigned aP[2][2][4];
        #pragma unroll
        for (int mf = 0; mf < 2; ++mf)
            #pragma unroll
            for (int kk2 = 0; kk2 < 2; ++kk2) {
                aP[mf][kk2][0] = packh2(cS[mf][2 * kk2][0],     cS[mf][2 * kk2][1]);
                aP[mf][kk2][1] = packh2(cS[mf][2 * kk2][2],     cS[mf][2 * kk2][3]);
                aP[mf][kk2][2] = packh2(cS[mf][2 * kk2 + 1][0], cS[mf][2 * kk2 + 1][1]);
                aP[mf][kk2][3] = packh2(cS[mf][2 * kk2 + 1][2], cS[mf][2 * kk2 + 1][3]);
            }

        #pragma unroll
        for (int g = 0; g < 2; ++g) {
            float cO[2][4][4];
            #pragma unroll
            for (int mf = 0; mf < 2; ++mf)
                #pragma unroll
                for (int nb = 0; nb < 4; ++nb)
                    #pragma unroll
                    for (int i = 0; i < 4; ++i) cO[mf][nb][i] = 0.f;
            #pragma unroll
            for (int kk2 = 0; kk2 < 2; ++kk2)
                #pragma unroll
                for (int nbl = 0; nbl < 4; ++nbl) {
                    unsigned bv2[2];
                    ldsm2t(bv2, Vb + (kk2 * 16 + l15) * PS + (g * 4 + nbl) * 8);
                    #pragma unroll
                    for (int mf = 0; mf < 2; ++mf)
                        mma16(cO[mf][nbl], aP[mf][kk2], bv2[0], bv2[1]);
                }
            #pragma unroll
            for (int mf = 0; mf < 2; ++mf)
                #pragma unroll
                for (int nbl = 0; nbl < 4; ++nbl) {
                    int hdc = (g * 4 + nbl) * 8 + 2 * tig;
                    if (hdc < HDD) {
                        int n = h * HDD + hdc;
                        #pragma unroll
                        for (int hs2 = 0; hs2 < 2; ++hs2) {
                            int r = br * LL + mf * 16 + gid + hs2 * 8;
                            *(__half2*)&Xsh[r * HS + n] =
                                __floats2half2_rn(cO[mf][nbl][2 * hs2],
                                                  cO[mf][nbl][2 * hs2 + 1]);
                        }
                    }
                }
        }
    }
    __syncthreads();

    // ---- ctx2 = ctx @ [Wo|bo] -> CT (fp32 only; no fp16 copy, no extra sync) ----
    gemm_main(paX0, paX1, g_Wh[3] + (size_t)wn * 5 * 32 + lane, c);
    #pragma unroll
    for (int mf = 0; mf < 2; ++mf)
        #pragma unroll
        for (int nc = 0; nc < 5; ++nc) {
            int n = wn * 40 + nc * 8 + 2 * tig;
            if (n < DDIM) {
                #pragma unroll
                for (int h = 0; h < 2; ++h) {
                    int r = wm * 32 + mf * 16 + gid + h * 8;
                    *(float2*)&CT[r * 300 + n] =
                        make_float2(c[mf][nc][2 * h], c[mf][nc][2 * h + 1]);
                }
            }
        }

    // ---- scores from ctx directly: a[l] = sum_n tanh(ctx @ [Wova|bva])[l][n]*qw[n] ----
    gemm_main(paX0, paX1, g_Wh[4] + (size_t)wn * 5 * 32 + lane, c);
    {
        float qn0[5], qn1[5];
        #pragma unroll
        for (int nc = 0; nc < 5; ++nc) {
            int n = wn * 40 + nc * 8 + 2 * tig;
            qn0[nc] = (n < DDIM) ? qw[n] : 0.f;
            qn1[nc] = (n < DDIM) ? qw[n + 1] : 0.f;
        }
        float p[2][2];
        #pragma unroll
        for (int mf = 0; mf < 2; ++mf) { p[mf][0] = 0.f; p[mf][1] = 0.f; }
        #pragma unroll
        for (int mf = 0; mf < 2; ++mf)
            #pragma unroll
            for (int nc = 0; nc < 5; ++nc)
                #pragma unroll
                for (int i = 0; i < 4; ++i) {
                    float qv = (i & 1) ? qn1[nc] : qn0[nc];
                    float tv = tanh_fast(c[mf][nc][i]);
                    p[mf][i >> 1] = fmaf(tv, qv, p[mf][i >> 1]);
                }
        #pragma unroll
        for (int mf = 0; mf < 2; ++mf)
            #pragma unroll
            for (int h = 0; h < 2; ++h) {
                float v = p[mf][h];
                v += __shfl_xor_sync(0xffffffffu, v, 1);
                v += __shfl_xor_sync(0xffffffffu, v, 2);
                p[mf][h] = v;
            }
        if (tig == 0) {
            #pragma unroll
            for (int mf = 0; mf < 2; ++mf)
                #pragma unroll
                for (int h = 0; h < 2; ++h) {
                    int r = wm * 32 + mf * 16 + gid + h * 8;
                    SP[wn * MT + r] = p[mf][h];
                }
        }
    }
    __syncthreads();
    if (tid < MT) {
        float s = 0.f;
        #pragma unroll
        for (int w = 0; w < 8; ++w) s += SP[w * MT + tid];
        SA[tid] = s;
    }
    __syncthreads();

    if (wid < 2) {      // one warp per batch row
        float v = SA[wid * LL + lane];
        float m = v;
        #pragma unroll
        for (int o = 16; o; o >>= 1) m = fmaxf(m, __shfl_xor_sync(0xffffffffu, m, o));
        float e = __expf(v - m);
        float sum = e;
        #pragma unroll
        for (int o = 16; o; o >>= 1) sum += __shfl_xor_sync(0xffffffffu, sum, o);
        SAL[wid * LL + lane] = e / sum;
    }
    __syncthreads();

    for (int idx = tid; idx < 2 * DDIM; idx += GT) {
        int bb = idx / DDIM, d = idx - bb * DDIM;
        float o = 0.f;
        #pragma unroll
        for (int l = 0; l < LL; ++l)
            o = fmaf(SAL[bb * LL + l], CT[(bb * LL + l) * 300 + d], o);
        out[(size_t)(blockIdx.x * 2 + bb) * DDIM + d] = o;
    }
}

extern "C" void kernel_launch(void* const* d_in, const int* in_sizes, int n_in,
                              void* d_out, int out_size) {
    const int*   title = (const int*)  d_in[0];
    const float* emb   = (const float*)d_in[1];
    const float* pos   = (const float*)d_in[2];
    const float* Wq    = (const float*)d_in[3];
    const float* bq    = (const float*)d_in[4];
    const float* Wk    = (const float*)d_in[5];
    const float* bk    = (const float*)d_in[6];
    const float* Wv    = (const float*)d_in[7];
    const float* bv    = (const float*)d_in[8];
    const float* Wo    = (const float*)d_in[9];
    const float* bo    = (const float*)d_in[10];
    const float* Va    = (const float*)d_in[11];
    const float* ba    = (const float*)d_in[12];
    const float* qw    = (const float*)d_in[13];
    float* out = (float*)d_out;

    cudaFuncSetAttribute(fused_kernel,
                         cudaFuncAttributeMaxDynamicSharedMemorySize, SMEM_BYTES);

    prep_wova<<<DDIM, 320>>>(Va, Wo, bo, ba);

    dim3 pgrid(48, 5);
    prep_pack<<<pgrid, 256>>>(Wq, Wk, Wv, Wo, bq, bk, bv, bo);

    fused_kernel<<<BB * LL / MT, GT, SMEM_BYTES>>>(title, emb, pos, qw, out);
}

// round 17
// speedup vs baseline: 1.4797x; 1.0045x over previous
#include <cuda_runtime.h>
#include <cuda_fp16.h>
#include <math.h>

#define BB 4096
#define LL 32
#define HH 6
#define DDIM 300
#define HDD 50
#define NKC16 19       // k-chunks of 16 (K padded to 304; col 300 = bias via x[...,300]=1)
#define HS 328         // half-stride of flat X rows: conflict-free frag loads
#define PS 392         // half-stride of head-padded Q/K/V rows (6*64 + 8 pad)
#define MT 64          // rows per CTA = 2 batch rows
#define GT 512         // 16 warps: 2 in M x 8 in N; warp tile 32 x 40

// Fragment-packed fp16 weights; m: Wq*rs, Wk, Wv, Wo, Wova  (bias in k=300 col)
#define WB16 (NKC16 * 8 * 5 * 32)
__device__ uint2 g_Wh[5][WB16];
__device__ float g_Wova[DDIM * DDIM];
__device__ float g_bva[DDIM];

// smem byte offsets
#define X_OFF   0           // half [64][328] : x -> ctx  (col 300 = 1.0)
#define QP_OFF  41984       // half [64][392] head-padded Q
#define KP_OFF  92160       // half [64][392] head-padded K
#define VP_OFF  142336      // half [64][392] head-padded V
#define CT_OFF  92160       // float [64][300] ctx2 fp32 (overlays K/V after attention)
#define SP_OFF  192512      // float [8][64]
#define SA_OFF  194560      // float [64]
#define SAL_OFF 194816      // float [64]
#define SMEM_BYTES 195072

__device__ __forceinline__ float tanh_fast(float x) {
    float y;
    asm("tanh.approx.f32 %0, %1;" : "=f"(y) : "f"(x));
    return y;
}

__device__ __forceinline__ void mma16(float c[4], const unsigned a[4],
                                      unsigned b0, unsigned b1) {
    asm volatile(
        "mma.sync.aligned.m16n8k16.row.col.f32.f16.f16.f32 "
        "{%0,%1,%2,%3},{%4,%5,%6,%7},{%8,%9},{%0,%1,%2,%3};"
        : "+f"(c[0]), "+f"(c[1]), "+f"(c[2]), "+f"(c[3])
        : "r"(a[0]), "r"(a[1]), "r"(a[2]), "r"(a[3]), "r"(b0), "r"(b1));
}

__device__ __forceinline__ void ldsm4(unsigned a[4], const __half* p) {
    unsigned addr = (unsigned)__cvta_generic_to_shared(p);
    asm volatile("ldmatrix.sync.aligned.m8n8.x4.shared.b16 {%0,%1,%2,%3}, [%4];"
                 : "=r"(a[0]), "=r"(a[1]), "=r"(a[2]), "=r"(a[3]) : "r"(addr));
}

__device__ __forceinline__ void ldsm2(unsigned b[2], const __half* p) {
    unsigned addr = (unsigned)__cvta_generic_to_shared(p);
    asm volatile("ldmatrix.sync.aligned.m8n8.x2.shared.b16 {%0,%1}, [%2];"
                 : "=r"(b[0]), "=r"(b[1]) : "r"(addr));
}

__device__ __forceinline__ void ldsm2t(unsigned b[2], const __half* p) {
    unsigned addr = (unsigned)__cvta_generic_to_shared(p);
    asm volatile("ldmatrix.sync.aligned.m8n8.x2.trans.shared.b16 {%0,%1}, [%2];"
                 : "=r"(b[0]), "=r"(b[1]) : "r"(addr));
}

__device__ __forceinline__ unsigned packh2(float lo, float hi) {
    __half2 h = __floats2half2_rn(lo, hi);
    return *(unsigned*)&h;
}

// ---- prep 1: Wova = Va @ Wo, 4 rows per block (coalesced Wo reads, 4-deep ILP) ----
__global__ void prep_wova(const float* __restrict__ Va, const float* __restrict__ Wo,
                          const float* __restrict__ bo, const float* __restrict__ ba) {
    __shared__ float sVa[4][DDIM];
    __shared__ float sred[4][10];
    const int n0 = blockIdx.x * 4;      // grid 75
    const int t = threadIdx.x;          // 320 threads
    for (int i = t; i < 4 * DDIM; i += 320) {
        int rr = i / DDIM, cc = i - rr * DDIM;
        sVa[rr][cc] = Va[(n0 + rr) * DDIM + cc];
    }
    __syncthreads();
    if (t < DDIM) {
        float a0 = 0.f, a1 = 0.f, a2 = 0.f, a3 = 0.f;
        #pragma unroll 4
        for (int m = 0; m < DDIM; ++m) {
            float w = Wo[m * DDIM + t];
            a0 = fmaf(sVa[0][m], w, a0);
            a1 = fmaf(sVa[1][m], w, a1);
            a2 = fmaf(sVa[2][m], w, a2);
            a3 = fmaf(sVa[3][m], w, a3);
        }
        g_Wova[(n0 + 0) * DDIM + t] = a0;
        g_Wova[(n0 + 1) * DDIM + t] = a1;
        g_Wova[(n0 + 2) * DDIM + t] = a2;
        g_Wova[(n0 + 3) * DDIM + t] = a3;
    }
    // bva[n] = sum_t Va[n][t]*bo[t] + ba[n]
    float bt = (t < DDIM) ? bo[t] : 0.f;
    #pragma unroll
    for (int rr = 0; rr < 4; ++rr) {
        float pb = (t < DDIM) ? sVa[rr][t] * bt : 0.f;
        #pragma unroll
        for (int o = 16; o; o >>= 1) pb += __shfl_xor_sync(0xffffffffu, pb, o);
        if ((t & 31) == 0) sred[rr][t >> 5] = pb;
    }
    __syncthreads();
    if (t < 4) {
        float s = 0.f;
        #pragma unroll
        for (int w = 0; w < 10; ++w) s += sred[t][w];
        g_bva[n0 + t] = s + ba[n0 + t];
    }
}

// value of augmented weight matrix m at (n,k): k<300 -> W, k==300 -> bias, else 0
__device__ __forceinline__ float wval(int m, int n, int k,
                                      const float* src, const float* bias, float scale) {
    if (n >= DDIM) return 0.f;
    if (k < DDIM)  return ((m == 4) ? g_Wova[n * DDIM + k] : src[n * DDIM + k]) * scale;
    if (k == DDIM) return ((m == 4) ? g_bva[n] : bias[n]) * scale;
    return 0.f;
}

// ---- prep 2: fragment packing (bias col + rs folding) ----
__global__ void prep_pack(const float* __restrict__ Wq, const float* __restrict__ Wk,
                          const float* __restrict__ Wv, const float* __restrict__ Wo,
                          const float* __restrict__ bq, const float* __restrict__ bk,
                          const float* __restrict__ bv, const float* __restrict__ bo) {
    const int m = blockIdx.y;
    const float* src; const float* bias;
    switch (m) {
        case 0: src = Wq; bias = bq; break;
        case 1: src = Wk; bias = bk; break;
        case 2: src = Wv; bias = bv; break;
        case 3: src = Wo; bias = bo; break;
        default: src = Wo; bias = bo; break;   // m=4 uses g_Wova/g_bva inside wval
    }
    const float scale = (m == 0) ? rsqrtf((float)HDD) : 1.f;
    uint2* dst = g_Wh[m];
    for (int idx = blockIdx.x * blockDim.x + threadIdx.x; idx < WB16;
         idx += gridDim.x * blockDim.x) {
        int lane = idx & 31;
        int t1   = idx >> 5;
        int nc   = t1 % 5;
        int t2   = t1 / 5;
        int wn   = t2 & 7;
        int kc   = t2 >> 3;
        int gid = lane >> 2, tig = lane & 3;
        int n = wn * 40 + nc * 8 + gid;
        int k = kc * 16 + 2 * tig;
        uint2 f;
        f.x = packh2(wval(m, n, k,     src, bias, scale),
                     wval(m, n, k + 1, src, bias, scale));
        f.y = packh2(wval(m, n, k + 8, src, bias, scale),
                     wval(m, n, k + 9, src, bias, scale));
        dst[idx] = f;
    }
}

// GEMM mainloop: warp tile 32x40, A via ldmatrix.x4, B depth-1 prefetch
__device__ __forceinline__ void gemm_main(const __half* __restrict__ pa0,
                                          const __half* __restrict__ pa1,
                                          const uint2* __restrict__ wb0,
                                          float c[2][5][4]) {
    #pragma unroll
    for (int mf = 0; mf < 2; ++mf)
        #pragma unroll
        for (int nc = 0; nc < 5; ++nc)
            #pragma unroll
            for (int i = 0; i < 4; ++i) c[mf][nc][i] = 0.f;

    uint2 bcur[5];
    #pragma unroll
    for (int nc = 0; nc < 5; ++nc) bcur[nc] = wb0[nc * 32];

    #pragma unroll 2
    for (int kc = 0; kc < NKC16; ++kc) {
        uint2 bnxt[5];
        if (kc + 1 < NKC16) {
            const uint2* w2 = wb0 + (size_t)(kc + 1) * (8 * 5 * 32);
            #pragma unroll
            for (int nc = 0; nc < 5; ++nc) bnxt[nc] = w2[nc * 32];
        }
        unsigned a[2][4];
        ldsm4(a[0], pa0 + kc * 16);
        ldsm4(a[1], pa1 + kc * 16);
        #pragma unroll
        for (int nc = 0; nc < 5; ++nc)
            #pragma unroll
            for (int mf = 0; mf < 2; ++mf)
                mma16(c[mf][nc], a[mf], bcur[nc].x, bcur[nc].y);
        #pragma unroll
        for (int nc = 0; nc < 5; ++nc) bcur[nc] = bnxt[nc];
    }
}

__global__ __launch_bounds__(GT, 1)
void fused_kernel(const int* __restrict__ title,
                  const float* __restrict__ emb,
                  const float* __restrict__ pos,
                  const float* __restrict__ qw,
                  float* __restrict__ out) {
    extern __shared__ char smraw[];
    __half* Xsh = (__half*)(smraw + X_OFF);
    __half* QP  = (__half*)(smraw + QP_OFF);
    __half* KP  = (__half*)(smraw + KP_OFF);
    __half* VP  = (__half*)(smraw + VP_OFF);
    float*  CT  = (float*)(smraw + CT_OFF);     // stride 300
    float*  SP  = (float*)(smraw + SP_OFF);
    float*  SA  = (float*)(smraw + SA_OFF);
    float*  SAL = (float*)(smraw + SAL_OFF);
    __shared__ int toks[MT];

    const int tid = threadIdx.x;
    const int lane = tid & 31, wid = tid >> 5;
    const int gid = lane >> 2, tig = lane & 3;
    const int wm = wid >> 3, wn = wid & 7;     // 2 x 8 warp grid
    const int r0 = blockIdx.x * MT;

    const int lrow = (lane & 15);
    const int lcol = (lane >> 4) << 3;

    if (tid < MT) toks[tid] = title[r0 + tid];
    __syncthreads();

    // ---- zero ONLY pad cols (50..63 per head) of QP and KP ----
    // (Q pad x K pad feeds S and 0*NaN=NaN, so both need cleaning; VP pads only
    //  pollute output cols >= 50 which are never stored)
    {
        const __half2 z2 = __floats2half2_rn(0.f, 0.f);
        for (int i = tid; i < MT * 42; i += GT) {       // 42 = 6 heads * 7 half2
            int r = i / 42, s = i - r * 42;
            int h = s / 7, o = s - h * 7;
            int col = h * 64 + 50 + 2 * o;
            *(__half2*)&QP[r * PS + col] = z2;
            *(__half2*)&KP[r * PS + col] = z2;
        }
    }

    // ---- gather x = fp16(emb[tok] + pos); col 300 = 1.0 (bias lane), rest 0 ----
    for (int idx = tid; idx < MT * 82; idx += GT) {
        int r = idx / 82, j = idx - r * 82;
        uint2 o = make_uint2(0u, 0u);
        if (j < 75) {
            float4 e = *(const float4*)&emb[(size_t)toks[r] * DDIM + 4 * j];
            float4 p = *(const float4*)&pos[(r & (LL - 1)) * DDIM + 4 * j];
            __half2 h0 = __floats2half2_rn(e.x + p.x, e.y + p.y);
            __half2 h1 = __floats2half2_rn(e.z + p.z, e.w + p.w);
            o.x = *(unsigned*)&h0;
            o.y = *(unsigned*)&h1;
        } else if (j == 75) {
            o.x = packh2(1.f, 0.f);           // col 300 = 1.0
        }
        *(uint2*)&Xsh[r * HS + 4 * j] = o;
    }
    __syncthreads();

    float c[2][5][4];
    const __half* paX0 = Xsh + (wm * 32 + lrow) * HS + lcol;
    const __half* paX1 = Xsh + (wm * 32 + 16 + lrow) * HS + lcol;

    // hoisted head-col mapping for the 3 QKV epilogues
    int ncol[5];
    bool nok[5];
    #pragma unroll
    for (int nc = 0; nc < 5; ++nc) {
        int n = wn * 40 + nc * 8 + 2 * tig;
        nok[nc] = (n < DDIM);
        int hh = n / HDD;
        ncol[nc] = hh * 64 + (n - HDD * hh);
    }

    // ---- K = x @ [Wk|bk] -> KP (head-padded); bias via mma ----
    gemm_main(paX0, paX1, g_Wh[1] + (size_t)wn * 5 * 32 + lane, c);
    #pragma unroll
    for (int mf = 0; mf < 2; ++mf)
        #pragma unroll
        for (int nc = 0; nc < 5; ++nc)
            if (nok[nc]) {
                #pragma unroll
                for (int h = 0; h < 2; ++h) {
                    int r = wm * 32 + mf * 16 + gid + h * 8;
                    *(__half2*)&KP[r * PS + ncol[nc]] =
                        __floats2half2_rn(c[mf][nc][2 * h], c[mf][nc][2 * h + 1]);
                }
            }

    // ---- V = x @ [Wv|bv] -> VP ----
    gemm_main(paX0, paX1, g_Wh[2] + (size_t)wn * 5 * 32 + lane, c);
    #pragma unroll
    for (int mf = 0; mf < 2; ++mf)
        #pragma unroll
        for (int nc = 0; nc < 5; ++nc)
            if (nok[nc]) {
                #pragma unroll
                for (int h = 0; h < 2; ++h) {
                    int r = wm * 32 + mf * 16 + gid + h * 8;
                    *(__half2*)&VP[r * PS + ncol[nc]] =
                        __floats2half2_rn(c[mf][nc][2 * h], c[mf][nc][2 * h + 1]);
                }
            }

    // ---- Q = x @ [Wq*rs|bq*rs] -> QP ----
    gemm_main(paX0, paX1, g_Wh[0] + (size_t)wn * 5 * 32 + lane, c);
    #pragma unroll
    for (int mf = 0; mf < 2; ++mf)
        #pragma unroll
        for (int nc = 0; nc < 5; ++nc)
            if (nok[nc]) {
                #pragma unroll
                for (int h = 0; h < 2; ++h) {
                    int r = wm * 32 + mf * 16 + gid + h * 8;
                    *(__half2*)&QP[r * PS + ncol[nc]] =
                        __floats2half2_rn(c[mf][nc][2 * h], c[mf][nc][2 * h + 1]);
                }
            }
    __syncthreads();

    // ---- tensor-core attention: 12 (brow,head) tasks; ctx -> Xsh (cols < 300) ----
    if (wid < 2 * HH) {
        int br = wid / HH, h = wid - HH * (wid / HH);
        const __half* Qb = QP + (br * LL) * PS + h * 64;
        const __half* Kb = KP + (br * LL) * PS + h * 64;
        const __half* Vb = VP + (br * LL) * PS + h * 64;
        const int l15 = lane & 15;

        float cS[2][4][4];
        #pragma unroll
        for (int mf = 0; mf < 2; ++mf)
            #pragma unroll
            for (int nb = 0; nb < 4; ++nb)
                #pragma unroll
                for (int i = 0; i < 4; ++i) cS[mf][nb][i] = 0.f;
        #pragma unroll
        for (int kk = 0; kk < 4; ++kk) {
            unsigned aq[2][4];
            ldsm4(aq[0], Qb + lrow * PS + lcol + kk * 16);
            ldsm4(aq[1], Qb + (16 + lrow) * PS + lcol + kk * 16);
            #pragma unroll
            for (int nb = 0; nb < 4; ++nb) {
                unsigned bk2[2];
                ldsm2(bk2, Kb + (nb * 8 + (lane & 7)) * PS + kk * 16 + ((l15 >> 3) << 3));
                #pragma unroll
                for (int mf = 0; mf < 2; ++mf)
                    mma16(cS[mf][nb], aq[mf], bk2[0], bk2[1]);
            }
        }

        #pragma unroll
        for (int mf = 0; mf < 2; ++mf)
            #pragma unroll
            for (int rsel = 0; rsel < 2; ++rsel) {
                float m = -1e30f;
                #pragma unroll
                for (int nb = 0; nb < 4; ++nb)
                    #pragma unroll
                    for (int p = 0; p < 2; ++p)
                        m = fmaxf(m, cS[mf][nb][2 * rsel + p]);
                m = fmaxf(m, __shfl_xor_sync(0xffffffffu, m, 1));
                m = fmaxf(m, __shfl_xor_sync(0xffffffffu, m, 2));
                float sum = 0.f;
                #pragma unroll
                for (int nb = 0; nb < 4; ++nb)
                    #pragma unroll
                    for (int p = 0; p < 2; ++p) {
                        float e = __expf(cS[mf][nb][2 * rsel + p] - m);
                        cS[mf][nb][2 * rsel + p] = e;
                        sum += e;
                    }
                sum += __shfl_xor_sync(0xffffffffu, sum, 1);
                sum += __shfl_xor_sync(0xffffffffu, sum, 2);
                float inv = 1.f / sum;
                #pragma unroll
                for (int nb = 0; nb < 4; ++nb)
                    #pragma unroll
                    for (int p = 0; p < 2; ++p)
                        cS[mf][nb][2 * rsel + p] *= inv;
            }

        unsigned aP[2][2][4];
        #pragma unroll
        for (int mf = 0; mf < 2; ++mf)
            #pragma unroll
            for (int kk2 = 0; kk2 < 2; ++kk2) {
                aP[mf][kk2][0] = packh2(cS[mf][2 * kk2][0],     cS[mf][2 * kk2][1]);
                aP[mf][kk2][1] = packh2(cS[mf][2 * kk2][2],     cS[mf][2 * kk2][3]);
                aP[mf][kk2][2] = packh2(cS[mf][2 * kk2 + 1][0], cS[mf][2 * kk2 + 1][1]);
                aP[mf][kk2][3] = packh2(cS[mf][2 * kk2 + 1][2], cS[mf][2 * kk2 + 1][3]);
            }

        #pragma unroll
        for (int g = 0; g < 2; ++g) {
            float cO[2][4][4];
            #pragma unroll
            for (int mf = 0; mf < 2; ++mf)
                #pragma unroll
                for (int nb = 0; nb < 4; ++nb)
                    #pragma unroll
                    for (int i = 0; i < 4; ++i) cO[mf][nb][i] = 0.f;
            #pragma unroll
            for (int kk2 = 0; kk2 < 2; ++kk2)
                #pragma unroll
                for (int nbl = 0; nbl < 4; ++nbl) {
                    unsigned bv2[2];
                    ldsm2t(bv2, Vb + (kk2 * 16 + l15) * PS + (g * 4 + nbl) * 8);
                    #pragma unroll
                    for (int mf = 0; mf < 2; ++mf)
                        mma16(cO[mf][nbl], aP[mf][kk2], bv2[0], bv2[1]);
                }
            #pragma unroll
            for (int mf = 0; mf < 2; ++mf)
                #pragma unroll
                for (int nbl = 0; nbl < 4; ++nbl) {
                    int hdc = (g * 4 + nbl) * 8 + 2 * tig;
                    if (hdc < HDD) {
                        int n = h * HDD + hdc;
                        #pragma unroll
                        for (int hs2 = 0; hs2 < 2; ++hs2) {
                            int r = br * LL + mf * 16 + gid + hs2 * 8;
                            *(__half2*)&Xsh[r * HS + n] =
                                __floats2half2_rn(cO[mf][nbl][2 * hs2],
                                                  cO[mf][nbl][2 * hs2 + 1]);
                        }
                    }
                }
        }
    }
    __syncthreads();

    // ---- ctx2 = ctx @ [Wo|bo] -> CT (fp32 only) ----
    gemm_main(paX0, paX1, g_Wh[3] + (size_t)wn * 5 * 32 + lane, c);
    #pragma unroll
    for (int mf = 0; mf < 2; ++mf)
        #pragma unroll
        for (int nc = 0; nc < 5; ++nc)
            if (nok[nc]) {
                int n = wn * 40 + nc * 8 + 2 * tig;
                #pragma unroll
                for (int h = 0; h < 2; ++h) {
                    int r = wm * 32 + mf * 16 + gid + h * 8;
                    *(float2*)&CT[r * 300 + n] =
                        make_float2(c[mf][nc][2 * h], c[mf][nc][2 * h + 1]);
                }
            }

    // ---- scores from ctx directly: a[l] = sum_n tanh(ctx @ [Wova|bva])[l][n]*qw[n] ----
    gemm_main(paX0, paX1, g_Wh[4] + (size_t)wn * 5 * 32 + lane, c);
    {
        float qn0[5], qn1[5];
        #pragma unroll
        for (int nc = 0; nc < 5; ++nc) {
            int n = wn * 40 + nc * 8 + 2 * tig;
            qn0[nc] = nok[nc] ? qw[n] : 0.f;
            qn1[nc] = nok[nc] ? qw[n + 1] : 0.f;
        }
        float p[2][2];
        #pragma unroll
        for (int mf = 0; mf < 2; ++mf) { p[mf][0] = 0.f; p[mf][1] = 0.f; }
        #pragma unroll
        for (int mf = 0; mf < 2; ++mf)
            #pragma unroll
            for (int nc = 0; nc < 5; ++nc)
                #pragma unroll
                for (int i = 0; i < 4; ++i) {
                    float qv = (i & 1) ? qn1[nc] : qn0[nc];
                    float tv = tanh_fast(c[mf][nc][i]);
                    p[mf][i >> 1] = fmaf(tv, qv, p[mf][i >> 1]);
                }
        #pragma unroll
        for (int mf = 0; mf < 2; ++mf)
            #pragma unroll
            for (int h = 0; h < 2; ++h) {
                float v = p[mf][h];
                v += __shfl_xor_sync(0xffffffffu, v, 1);
                v += __shfl_xor_sync(0xffffffffu, v, 2);
                p[mf][h] = v;
            }
        if (tig == 0) {
            #pragma unroll
            for (int mf = 0; mf < 2; ++mf)
                #pragma unroll
                for (int h = 0; h < 2; ++h) {
                    int r = wm * 32 + mf * 16 + gid + h * 8;
                    SP[wn * MT + r] = p[mf][h];
                }
        }
    }
    __syncthreads();
    if (tid < MT) {
        float s = 0.f;
        #pragma unroll
        for (int w = 0; w < 8; ++w) s += SP[w * MT + tid];
        SA[tid] = s;
    }
    __syncthreads();

    if (wid < 2) {      // one warp per batch row
        float v = SA[wid * LL + lane];
        float m = v;
        #pragma unroll
        for (int o = 16; o; o >>= 1) m = fmaxf(m, __shfl_xor_sync(0xffffffffu, m, o));
        float e = __expf(v - m);
        float sum = e;
        #pragma unroll
        for (int o = 16; o; o >>= 1) sum += __shfl_xor_sync(0xffffffffu, sum, o);
        SAL[wid * LL + lane] = e / sum;
    }
    __syncthreads();

    for (int idx = tid; idx < 2 * DDIM; idx += GT) {
        int bb = idx / DDIM, d = idx - bb * DDIM;
        float o = 0.f;
        #pragma unroll
        for (int l = 0; l < LL; ++l)
            o = fmaf(SAL[bb * LL + l], CT[(bb * LL + l) * 300 + d], o);
        out[(size_t)(blockIdx.x * 2 + bb) * DDIM + d] = o;
    }
}

extern "C" void kernel_launch(void* const* d_in, const int* in_sizes, int n_in,
                              void* d_out, int out_size) {
    const int*   title = (const int*)  d_in[0];
    const float* emb   = (const float*)d_in[1];
    const float* pos   = (const float*)d_in[2];
    const float* Wq    = (const float*)d_in[3];
    const float* bq    = (const float*)d_in[4];
    const float* Wk    = (const float*)d_in[5];
    const float* bk    = (const float*)d_in[6];
    const float* Wv    = (const float*)d_in[7];
    const float* bv    = (const float*)d_in[8];
    const float* Wo    = (const float*)d_in[9];
    const float* bo    = (const float*)d_in[10];
    const float* Va    = (const float*)d_in[11];
    const float* ba    = (const float*)d_in[12];
    const float* qw    = (const float*)d_in[13];
    float* out = (float*)d_out;

    cudaFuncSetAttribute(fused_kernel,
                         cudaFuncAttributeMaxDynamicSharedMemorySize, SMEM_BYTES);

    prep_wova<<<75, 320>>>(Va, Wo, bo, ba);

    dim3 pgrid(48, 5);
    prep_pack<<<pgrid, 256>>>(Wq, Wk, Wv, Wo, bq, bk, bv, bo);

    fused_kernel<<<BB * LL / MT, GT, SMEM_BYTES>>>(title, emb, pos, qw, out);
}